// round 13
// baseline (speedup 1.0000x reference)
#include <cuda_runtime.h>
#include <math.h>
#include <stdint.h>

// Problem constants (fixed by setup_inputs)
#define BS     8
#define HW     4096       // 64*64
#define VN     204        // hw // STEP
#define STEPV  20
#define PN     400
#define NPAIR  200        // PN/2 packed gt pairs
#define NT     128        // 4 warps
#define NBLK   592        // 148 SMs * 4  (best-measured config)
#define NWARPS (NBLK * 4)
#define CKV    4          // chunks per view: 3x128 points + 1x16 points
#define HITEMS (VN * CKV) // 816 heavy warp-items per sym batch
#define SLOTS  4          // sym batches staged simultaneously

// Scratch (no cudaMalloc). Zero at load; last block resets for graph replay.
__device__ double       g_acc[2];     // [0]=loss sum, [1]=value sum
__device__ unsigned int g_count = 0;

// Packed f32x2 FMA (Blackwell FFMA2 — only via PTX)
#define FMA2(d, a, b, c) \
    asm("fma.rn.f32x2 %0, %1, %2, %3;" : "=l"(d) : "l"(a), "l"(b), "l"(c))
#define UNPACK2(lo, hi, v) \
    asm("mov.b64 {%0, %1}, %2;" : "=r"(lo), "=r"(hi) : "l"(v))

__device__ __forceinline__ uint64_t pack2(float lo, float hi) {
    return (uint64_t)__float_as_uint(lo) | ((uint64_t)__float_as_uint(hi) << 32);
}

struct Pose { float R00,R01,R02,R10,R11,R12,R20,R21,R22,t0,t1,t2; };

__device__ __forceinline__ Pose pred_pose(const float* __restrict__ pred_r,
                                          const float* __restrict__ pred_t,
                                          int b, int pix)
{
    const float* prb = pred_r + (size_t)b * 4 * HW;
    float q0 = prb[pix], q1 = prb[HW+pix], q2 = prb[2*HW+pix], q3 = prb[3*HW+pix];
    const float inv = rsqrtf(q0*q0 + q1*q1 + q2*q2 + q3*q3);
    q0 *= inv; q1 *= inv; q2 *= inv; q3 *= inv;
    Pose P;
    P.R00 = 1.0f - 2.0f*(q2*q2 + q3*q3);
    P.R01 = 2.0f*q1*q2 - 2.0f*q0*q3;
    P.R02 = 2.0f*q0*q2 + 2.0f*q1*q3;
    P.R10 = 2.0f*q1*q2 + 2.0f*q3*q0;
    P.R11 = 1.0f - 2.0f*(q1*q1 + q3*q3);
    P.R12 = -2.0f*q0*q1 + 2.0f*q2*q3;
    P.R20 = -2.0f*q0*q2 + 2.0f*q1*q3;
    P.R21 = 2.0f*q0*q1 + 2.0f*q2*q3;
    P.R22 = 1.0f - 2.0f*(q1*q1 + q2*q2);
    const float* ptb = pred_t + (size_t)b * 3 * HW;
    P.t0 = ptb[pix]; P.t1 = ptb[HW+pix]; P.t2 = ptb[2*HW+pix];
    return P;
}

// ADD-S for NC chains: chain k covers points p_base + 32k + lane.
template<int NC>
__device__ __forceinline__ float adds_item(
    const ulonglong2* __restrict__ pa, const ulonglong2* __restrict__ pb,
    const float* __restrict__ mb, const Pose& P, int p_base, int lane)
{
    float pn[NC], mlo[NC], mhi[NC];
    uint64_t ax[NC], ay[NC], az[NC];
    bool act[NC];
    #pragma unroll
    for (int k = 0; k < NC; k++) {
        const int p = p_base + 32*k + lane;
        act[k] = (p < PN);
        const int pp = act[k] ? p : (PN - 1);
        const float x = mb[pp], y = mb[PN+pp], z = mb[2*PN+pp];
        const float px = P.R00*x + P.R01*y + P.R02*z + P.t0;
        const float py = P.R10*x + P.R11*y + P.R12*z + P.t1;
        const float pz = P.R20*x + P.R21*y + P.R22*z + P.t2;
        pn[k] = px*px + py*py + pz*pz;
        ax[k] = pack2(-2.0f*px, -2.0f*px);
        ay[k] = pack2(-2.0f*py, -2.0f*py);
        az[k] = pack2(-2.0f*pz, -2.0f*pz);
        mlo[k] = 3.4e38f; mhi[k] = 3.4e38f;
    }

    #pragma unroll 4
    for (int j = 0; j < NPAIR; j++) {
        const ulonglong2 A = pa[j];   // LDS.128 broadcast: (gx0,gx1),(gy0,gy1)
        const ulonglong2 B = pb[j];   // (gz0,gz1),(gn0,gn1)
        #pragma unroll
        for (int k = 0; k < NC; k++) {
            uint64_t t;
            FMA2(t, az[k], B.x, B.y);
            FMA2(t, ay[k], A.y, t);
            FMA2(t, ax[k], A.x, t);
            uint32_t lo, hi;
            UNPACK2(lo, hi, t);
            mlo[k] = fminf(mlo[k], __uint_as_float(lo));
            mhi[k] = fminf(mhi[k], __uint_as_float(hi));
        }
    }

    float s = 0.0f;
    #pragma unroll
    for (int k = 0; k < NC; k++)
        if (act[k])
            s += sqrtf(fmaxf(pn[k] + fminf(mlo[k], mhi[k]), 0.0f));
    return s;
}

__global__ __launch_bounds__(NT, 4) void loss_kernel(
    const float* __restrict__ pred_r,     // (bs,4,h,w)
    const float* __restrict__ pred_t,     // (bs,3,h,w)
    const float* __restrict__ pred_score, // (bs,h,w)
    const float* __restrict__ gt_r,       // (bs,3,3)
    const float* __restrict__ gt_t,       // (bs,3)
    const int*   __restrict__ cls_ids,    // (bs,)
    const float* __restrict__ model,      // (bs,3,P)
    float* __restrict__ out)
{
    const int tid  = threadIdx.x;
    const int wid  = tid >> 5;
    const int lane = tid & 31;
    const int wgid = blockIdx.x * 4 + wid;

    __shared__ ulonglong2 sA[SLOTS][NPAIR];   // (gx0,gx1),(gy0,gy1)
    __shared__ ulonglong2 sB[SLOTS][NPAIR];   // (gz0,gz1),(gn0,gn1)
    __shared__ double     redd[8];

    // Classify batches (broadcast LDGs, registers only)
    unsigned sym_mask = 0u, light_mask = 0u;
    #pragma unroll
    for (int b = 0; b < BS; b++) {
        const int c = cls_ids[b];
        const bool val = (c >= 0 && c <= 29);
        const bool sy  = (c==12 || c==15 || c==18 || c==19 || c==20);
        if (val &&  sy) sym_mask   |= (1u << b);
        if (val && !sy) light_mask |= (1u << b);
    }
    const int ns = __popc(sym_mask);
    const int nl = __popc(light_mask);
    const int L  = VN * nl;
    const int nwaves = (ns <= SLOTS) ? 1 : ((ns + SLOTS - 1) / SLOTS);

    double accL = 0.0, accV = 0.0;        // per-warp (uniform across lanes)
    const float invPN = 1.0f / (float)PN;

    for (int w = 0; w < nwaves; w++) {
        const int bi0 = w * SLOTS;
        int nsw = ns - bi0; if (nsw > SLOTS) nsw = SLOTS; if (nsw < 0) nsw = 0;

        if (w > 0) __syncthreads();   // previous wave's readers done (rare)
        // Stage packed gt pairs for ALL nsw batches, then ONE barrier.
        for (int idx = tid; idx < nsw * NPAIR; idx += NT) {
            const int slot = idx / NPAIR;
            const int j    = idx - slot * NPAIR;
            const int b    = __fns(sym_mask, 0, bi0 + slot + 1);
            const float r00 = gt_r[b*9+0], r01 = gt_r[b*9+1], r02 = gt_r[b*9+2];
            const float r10 = gt_r[b*9+3], r11 = gt_r[b*9+4], r12 = gt_r[b*9+5];
            const float r20 = gt_r[b*9+6], r21 = gt_r[b*9+7], r22 = gt_r[b*9+8];
            const float t0g = gt_t[b*3+0], t1g = gt_t[b*3+1], t2g = gt_t[b*3+2];
            const float* mb = model + (size_t)b * 3 * PN;
            const float x0 = mb[2*j],   y0 = mb[PN+2*j],   z0 = mb[2*PN+2*j];
            const float x1 = mb[2*j+1], y1 = mb[PN+2*j+1], z1 = mb[2*PN+2*j+1];
            const float gx0 = r00*x0 + r01*y0 + r02*z0 + t0g;
            const float gy0 = r10*x0 + r11*y0 + r12*z0 + t1g;
            const float gz0 = r20*x0 + r21*y0 + r22*z0 + t2g;
            const float gx1 = r00*x1 + r01*y1 + r02*z1 + t0g;
            const float gy1 = r10*x1 + r11*y1 + r12*z1 + t1g;
            const float gz1 = r20*x1 + r21*y1 + r22*z1 + t2g;
            sA[slot][j] = make_ulonglong2(pack2(gx0,gx1), pack2(gy0,gy1));
            sB[slot][j] = make_ulonglong2(pack2(gz0,gz1),
                                          pack2(gx0*gx0+gy0*gy0+gz0*gz0,
                                                gx1*gx1+gy1*gy1+gz1*gz1));
        }
        __syncthreads();

        // Unified stripe: [0, Hw) heavy items of this wave, then lights (wave 0)
        const int Hw = nsw * HITEMS;
        const int T  = Hw + ((w == 0) ? L : 0);

        for (int i = wgid; i < T; i += NWARPS) {
            if (i < Hw) {
                // ---------- Heavy (ADD-S) warp-item ----------
                const int slot = i / HITEMS;
                const int rem  = i - slot * HITEMS;
                const int v    = rem >> 2;        // CKV = 4
                const int ck   = rem & 3;
                const int b    = __fns(sym_mask, 0, bi0 + slot + 1);
                const float* mb = model + (size_t)b * 3 * PN;

                const int pix = v * STEPV;
                const Pose P = pred_pose(pred_r, pred_t, b, pix);
                const float sc = pred_score[(size_t)b * HW + pix];

                float s;
                if (ck < 3) s = adds_item<4>(sA[slot], sB[slot], mb, P, ck * 128, lane);
                else        s = adds_item<1>(sA[slot], sB[slot], mb, P, 384, lane);

                #pragma unroll
                for (int off = 16; off > 0; off >>= 1)
                    s += __shfl_xor_sync(0xFFFFFFFFu, s, off);

                const float part = s * invPN;
                float lc = part * sc;
                if (ck == 0) lc += -0.01f * logf(sc);  // log term once per view
                accL += (double)lc;
                accV += (double)part;
            } else {
                // ---------- Light (ADD) warp-item ----------
                const int l     = i - Hw;
                const int b_idx = l / VN;
                const int v     = l - b_idx * VN;
                const int b     = __fns(light_mask, 0, b_idx + 1);

                const float r00 = gt_r[b*9+0], r01 = gt_r[b*9+1], r02 = gt_r[b*9+2];
                const float r10 = gt_r[b*9+3], r11 = gt_r[b*9+4], r12 = gt_r[b*9+5];
                const float r20 = gt_r[b*9+6], r21 = gt_r[b*9+7], r22 = gt_r[b*9+8];
                const float t0g = gt_t[b*3+0], t1g = gt_t[b*3+1], t2g = gt_t[b*3+2];
                const float* mb = model + (size_t)b * 3 * PN;

                const int pix = v * STEPV;
                const Pose P = pred_pose(pred_r, pred_t, b, pix);
                const float sc = pred_score[(size_t)b * HW + pix];

                float s = 0.0f;
                for (int p = lane; p < PN; p += 32) {
                    const float x = mb[p], y = mb[PN+p], z = mb[2*PN+p];
                    const float dx = P.R00*x + P.R01*y + P.R02*z + P.t0 - (r00*x + r01*y + r02*z + t0g);
                    const float dy = P.R10*x + P.R11*y + P.R12*z + P.t1 - (r10*x + r11*y + r12*z + t1g);
                    const float dz = P.R20*x + P.R21*y + P.R22*z + P.t2 - (r20*x + r21*y + r22*z + t2g);
                    s += sqrtf(dx*dx + dy*dy + dz*dz);
                }
                #pragma unroll
                for (int off = 16; off > 0; off >>= 1)
                    s += __shfl_xor_sync(0xFFFFFFFFu, s, off);

                const float add_ij = s * invPN;
                accL += (double)(add_ij * sc - 0.01f * logf(sc));
                accV += (double)add_ij;
            }
        }
    }

    // ===== Per-warp -> block -> 2 atomics (benchmarked best tail) ============
    if (lane == 0) { redd[wid*2] = accL; redd[wid*2+1] = accV; }
    __syncthreads();

    if (tid == 0) {
        double Lacc = 0.0, Vacc = 0.0;
        #pragma unroll
        for (int ww = 0; ww < 4; ww++) { Lacc += redd[ww*2]; Vacc += redd[ww*2+1]; }
        const double scale = 1.0 / ((double)VN * (double)BS);
        atomicAdd(&g_acc[0], Lacc * scale);
        atomicAdd(&g_acc[1], Vacc * scale);
        __threadfence();
        const unsigned int old = atomicAdd(&g_count, 1u);
        if (old == (unsigned int)(NBLK - 1)) {
            __threadfence();
            const double gl = *(volatile double*)&g_acc[0];
            const double gv = *(volatile double*)&g_acc[1];
            float glf = (float)gl;
            const float gvf = (float)gv;
            if (isinf(glf) || isnan(glf)) glf = 0.0f;
            out[0] = glf + 0.0f * gvf;   // faithful to reference
            g_acc[0] = 0.0;
            g_acc[1] = 0.0;
            g_count  = 0u;
        }
    }
}

extern "C" void kernel_launch(void* const* d_in, const int* in_sizes, int n_in,
                              void* d_out, int out_size) {
    const float* pred_r     = (const float*)d_in[0];
    const float* pred_t     = (const float*)d_in[1];
    const float* pred_score = (const float*)d_in[2];
    const float* gt_r       = (const float*)d_in[3];
    const float* gt_t       = (const float*)d_in[4];
    const int*   cls_ids    = (const int*)  d_in[5];
    const float* model_xyz  = (const float*)d_in[6];
    float* out = (float*)d_out;

    loss_kernel<<<NBLK, NT>>>(pred_r, pred_t, pred_score, gt_r, gt_t,
                              cls_ids, model_xyz, out);
}